// round 2
// baseline (speedup 1.0000x reference)
#include <cuda_runtime.h>
#include <cuda_bf16.h>
#include <math.h>
#include <float.h>

// Problem constants (fixed shapes from reference setup_inputs)
#define BB 32
#define NN 300
#define MM 50

#define COST_POS 5.0
#define LAMBDA_POS 5.0
#define LAMBDA_CONF 2.0
#define LAMBDA_NOOBJ 0.5

// Scratch (no cudaMalloc allowed): cost matrices + per-image partial losses
__device__ double g_cost[BB * MM * NN];   // 3.84 MB, L2-resident
__device__ double g_part[BB * 3];

// One warp per image. Warp-synchronous JV (Jonker-Volgenant shortest augmenting
// path), bit-matching the numpy float64 reference comparison chain.
__global__ void __launch_bounds__(32, 1)
detloss_solve_kernel(const float* __restrict__ pred_c,  // [B,N,2]
                     const float* __restrict__ conf,    // [B,N]
                     const float* __restrict__ gt_c)    // [B,M,2]
{
    const int b    = blockIdx.x;
    const int lane = threadIdx.x;

    const float* pc = pred_c + b * NN * 2;
    const float* cf = conf   + b * NN;
    const float* gc = gt_c   + b * MM * 2;
    double* cost = g_cost + (size_t)b * MM * NN;

    __shared__ double sh_shortest[NN];
    __shared__ double sh_v[NN];
    __shared__ double sh_u[MM];
    __shared__ int    sh_pathback[NN];
    __shared__ int    sh_row4col[NN];
    __shared__ int    sh_col4row[MM];
    __shared__ unsigned char sh_SR[MM];
    __shared__ unsigned char sh_rem[NN];
    __shared__ unsigned char sh_matched[NN];

    // ---- Build transposed cost matrix: rows = gt (M), cols = pred (N) ----
    // cost[m][j] = 5.0 * (|px-gx| + |py-gy|) + 1.0 * (-sigmoid(conf_j))
    // Match numpy float64 op order; forbid FMA contraction with explicit intrinsics.
    for (int j = lane; j < NN; j += 32) {
        double x   = (double)cf[j];
        double sig = 1.0 / (1.0 + exp(-x));
        double px  = (double)pc[2 * j];
        double py  = (double)pc[2 * j + 1];
        #pragma unroll 5
        for (int m = 0; m < MM; m++) {
            double dx = fabs(__dadd_rn(px, -(double)gc[2 * m]));
            double dy = fabs(__dadd_rn(py, -(double)gc[2 * m + 1]));
            double cpos = __dadd_rn(dx, dy);
            cost[m * NN + j] = __dadd_rn(__dmul_rn(COST_POS, cpos), -sig);
        }
    }

    for (int j = lane; j < NN; j += 32) {
        sh_v[j] = 0.0;
        sh_row4col[j] = -1;
        sh_matched[j] = 0;
    }
    for (int m = lane; m < MM; m += 32) {
        sh_u[m] = 0.0;
        sh_col4row[m] = -1;
    }
    __syncwarp();

    // ---- JV shortest augmenting path, one augmenting row at a time ----
    for (int cur = 0; cur < MM; cur++) {
        for (int j = lane; j < NN; j += 32) {
            sh_shortest[j] = DBL_MAX;
            sh_pathback[j] = -1;
            sh_rem[j] = 1;
        }
        for (int m = lane; m < MM; m += 32) sh_SR[m] = 0;
        __syncwarp();

        int i = cur;
        double minval = 0.0;
        int sink = -1;

        while (true) {
            if (lane == 0) sh_SR[i] = 1;
            double ui = sh_u[i];
            const double* crow = cost + i * NN;

            // relax remaining columns owned by this lane + local argmin
            double bestv = DBL_MAX;
            int    bestj = NN;  // sentinel > any real column
            for (int j = lane; j < NN; j += 32) {
                if (sh_rem[j]) {
                    // exact numpy order: ((min_val + c) - u) - v ; pure adds (no FMA risk)
                    double nc = ((minval + crow[j]) - ui) - sh_v[j];
                    double s  = sh_shortest[j];
                    if (nc < s) {
                        s = nc;
                        sh_shortest[j] = nc;
                        sh_pathback[j] = i;
                    }
                    if (s < bestv) { bestv = s; bestj = j; }
                }
            }
            // warp argmin, tie-break lowest column index (numpy first-occurrence)
            #pragma unroll
            for (int off = 16; off; off >>= 1) {
                double ov = __shfl_xor_sync(0xffffffffu, bestv, off);
                int    oj = __shfl_xor_sync(0xffffffffu, bestj, off);
                if (ov < bestv || (ov == bestv && oj < bestj)) { bestv = ov; bestj = oj; }
            }
            minval = bestv;
            int jst = bestj;

            __syncwarp();
            if (lane == 0) sh_rem[jst] = 0;
            __syncwarp();

            int r = sh_row4col[jst];
            if (r < 0) { sink = jst; break; }
            i = r;
        }

        __syncwarp();
        // dual updates (exact numpy op order)
        if (lane == 0) sh_u[cur] += minval;
        for (int m = lane; m < MM; m += 32) {
            if (m != cur && sh_SR[m]) {
                double t = minval - sh_shortest[sh_col4row[m]];
                sh_u[m] += t;
            }
        }
        for (int j = lane; j < NN; j += 32) {
            if (!sh_rem[j]) {  // SC == removed set
                double t = minval - sh_shortest[j];
                sh_v[j] -= t;
            }
        }
        __syncwarp();

        // augment along the path (sequential, lane 0)
        if (lane == 0) {
            int j = sink;
            while (true) {
                int ii = sh_pathback[j];
                sh_row4col[j] = ii;
                int t = sh_col4row[ii];
                sh_col4row[ii] = j;
                j = t;
                if (ii == cur) break;
            }
        }
        __syncwarp();
    }

    // ---- Loss partials for this image ----
    double pos = 0.0, obj = 0.0, noobj = 0.0;
    for (int m = lane; m < MM; m += 32) {
        int j = sh_col4row[m];
        sh_matched[j] = 1;
        double dx = fabs((double)pc[2 * j]     - (double)gc[2 * m]);
        double dy = fabs((double)pc[2 * j + 1] - (double)gc[2 * m + 1]);
        pos += dx + dy;
        // softplus(-logit), stable
        double x = -(double)cf[j];
        obj += fmax(x, 0.0) + log1p(exp(-fabs(x)));
    }
    __syncwarp();
    for (int j = lane; j < NN; j += 32) {
        if (!sh_matched[j]) {
            double x = (double)cf[j];
            noobj += fmax(x, 0.0) + log1p(exp(-fabs(x)));
        }
    }
    #pragma unroll
    for (int off = 16; off; off >>= 1) {
        pos   += __shfl_xor_sync(0xffffffffu, pos,   off);
        obj   += __shfl_xor_sync(0xffffffffu, obj,   off);
        noobj += __shfl_xor_sync(0xffffffffu, noobj, off);
    }
    if (lane == 0) {
        g_part[b * 3 + 0] = pos   / (double)(MM * 2);  // mean over (M,D)
        g_part[b * 3 + 1] = obj   / (double)MM;        // mean over M
        g_part[b * 3 + 2] = noobj / (double)(NN - MM); // / (N-M)
    }
}

__global__ void detloss_finalize_kernel(float* __restrict__ out)
{
    int lane = threadIdx.x;  // 32 threads, lane b sums image b
    double p = 0.0, o = 0.0, q = 0.0;
    if (lane < BB) {
        p = g_part[lane * 3 + 0];
        o = g_part[lane * 3 + 1];
        q = g_part[lane * 3 + 2];
    }
    #pragma unroll
    for (int off = 16; off; off >>= 1) {
        p += __shfl_xor_sync(0xffffffffu, p, off);
        o += __shfl_xor_sync(0xffffffffu, o, off);
        q += __shfl_xor_sync(0xffffffffu, q, off);
    }
    if (lane == 0) {
        float lp = (float)(LAMBDA_POS   * p / (double)BB);
        float lo = (float)(LAMBDA_CONF  * o / (double)BB);
        float ln = (float)(LAMBDA_NOOBJ * q / (double)BB);
        out[0] = lp;
        out[1] = lo;
        out[2] = ln;
        out[3] = lp + lo + ln;
        out[4] = (float)MM;  // n_matched = M
    }
}

extern "C" void kernel_launch(void* const* d_in, const int* in_sizes, int n_in,
                              void* d_out, int out_size)
{
    // metadata order: pred_centroids, pred_logits, pred_conf, gt_centroids, gt_classes
    const float* pred_c = (const float*)d_in[0];
    // d_in[1] (pred_logits) unused by the reference loss
    const float* conf   = (const float*)d_in[2];
    const float* gt_c   = (const float*)d_in[3];
    // d_in[4] (gt_classes) unused
    float* out = (float*)d_out;

    detloss_solve_kernel<<<BB, 32>>>(pred_c, conf, gt_c);
    detloss_finalize_kernel<<<1, 32>>>(out);
}

// round 3
// speedup vs baseline: 1.7740x; 1.7740x over previous
#include <cuda_runtime.h>
#include <cuda_bf16.h>
#include <math.h>
#include <float.h>

// Fixed problem shapes
#define BB 32
#define NN 300
#define MM 50
#define NSLOT 10          // columns per lane (lanes 0..11 own 10, lanes 12..31 own 9)

#define LAMBDA_POS 5.0
#define LAMBDA_CONF 2.0
#define LAMBDA_NOOBJ 0.5

#define FULLMASK 0xffffffffu

// Cross-block scratch (no cudaMalloc allowed)
__device__ double g_part[BB * 3];
__device__ int    g_done = 0;

// ---- order-preserving double <-> u64 key transforms ----
__device__ __forceinline__ unsigned long long d2key(double d) {
    long long b = __double_as_longlong(d);
    // d >= 0 (sign bit 0): key = b | 0x800...  ; d < 0: key = ~b
    unsigned long long ub = (unsigned long long)b;
    return (b >= 0) ? (ub ^ 0x8000000000000000ULL) : ~ub;
}
__device__ __forceinline__ double key2d(unsigned long long k) {
    unsigned long long b = (k & 0x8000000000000000ULL) ? (k ^ 0x8000000000000000ULL) : ~k;
    return __longlong_as_double((long long)b);
}
__device__ __forceinline__ unsigned long long umin64(unsigned long long a, unsigned long long b) {
    return a < b ? a : b;
}
__device__ __forceinline__ double softplus_d(double x) {
    return fmax(x, 0.0) + log1p(exp(-fabs(x)));
}

// Dynamic smem layout (doubles first for alignment)
//   sc    [MM*NN]  cost matrix, row-major [m][j]
//   spath [NN]     exact shortest value of removed/improved columns
//   urow  [NN]     u[row4col[j]] cache (valid for matched j)
//   su    [MM]     dual u
//   pb    [NN]     pathback
//   r4c   [NN]     row4col (-1 = unmatched)
//   c4r   [MM]     col4row
#define SMEM_DOUBLES (MM * NN + NN + NN + MM)
#define SMEM_INTS    (NN + NN + MM)
#define SMEM_BYTES   (SMEM_DOUBLES * 8 + SMEM_INTS * 4)

__global__ void __launch_bounds__(32, 1)
detloss_kernel(const float* __restrict__ pred_c,  // [B,N,2]
               const float* __restrict__ conf,    // [B,N]
               const float* __restrict__ gt_c,    // [B,M,2]
               float* __restrict__ out)           // [5]
{
    const int b    = blockIdx.x;
    const int lane = threadIdx.x;

    const float* pc = pred_c + b * NN * 2;
    const float* cf = conf   + b * NN;
    const float* gc = gt_c   + b * MM * 2;

    extern __shared__ double dyn[];
    double* sc     = dyn;
    double* spath  = sc + MM * NN;
    double* urow   = spath + NN;
    double* su     = urow + NN;
    int*    pb     = (int*)(su + MM);
    int*    r4c    = pb + NN;
    int*    c4r    = r4c + NN;

    // ---- Build cost matrix into smem: cost[m][j] = 5*L1(pred_j, gt_m) - sigmoid(conf_j)
    // Column j is built AND consumed by lane (j % 32): no sync needed on sc.
    #pragma unroll
    for (int k = 0; k < NSLOT; k++) {
        int j = k * 32 + lane;
        if (j < NN) {
            double x   = (double)cf[j];
            double sig = 1.0 / (1.0 + exp(-x));
            double px  = (double)pc[2 * j];
            double py  = (double)pc[2 * j + 1];
            for (int m = 0; m < MM; m++) {
                double dx = fabs(px - (double)gc[2 * m]);
                double dy = fabs(py - (double)gc[2 * m + 1]);
                sc[m * NN + j] = 5.0 * (dx + dy) - sig;
            }
        }
    }
    // init shared state
    for (int j = lane; j < NN; j += 32) { r4c[j] = -1; urow[j] = 0.0; }
    for (int m = lane; m < MM; m += 32) { su[m] = 0.0; c4r[m] = -1; }
    __syncwarp();

    // per-lane register state
    double v[NSLOT];
    #pragma unroll
    for (int k = 0; k < NSLOT; k++) v[k] = 0.0;
    const unsigned validMask = (lane < 12) ? 0x3FFu : 0x1FFu;  // which slots map to j < 300

    // ---- JV: one augmenting row at a time ----
    for (int cur = 0; cur < MM; cur++) {
        unsigned long long skey[NSLOT];
        #pragma unroll
        for (int k = 0; k < NSLOT; k++) skey[k] = ~0ULL;
        unsigned rem = validMask;
        unsigned remRound = 0;
        unsigned long long SR = 1ULL << cur;

        int    i      = cur;
        double ui     = su[cur];
        double minval = 0.0;
        int    sink;

        while (true) {
            double a = minval - ui;
            const double* crow = sc + i * NN;

            // relax remaining columns owned by this lane
            #pragma unroll
            for (int k = 0; k < NSLOT; k++) {
                if (rem & (1u << k)) {
                    int j = k * 32 + lane;
                    double nc = a + (crow[j] - v[k]);
                    unsigned long long ck = (d2key(nc) & ~511ULL) | (unsigned)j;
                    if (ck < skey[k]) {
                        skey[k] = ck;
                        spath[j] = nc;   // exact value for dual updates
                        pb[j]   = i;
                    }
                }
            }
            // local min tree over 10 slots (u64 keys; index packed in low 9 bits)
            unsigned long long a0 = umin64(skey[0], skey[1]);
            unsigned long long a1 = umin64(skey[2], skey[3]);
            unsigned long long a2 = umin64(skey[4], skey[5]);
            unsigned long long a3 = umin64(skey[6], skey[7]);
            unsigned long long a4 = umin64(skey[8], skey[9]);
            unsigned long long mloc = umin64(umin64(umin64(a0, a1), umin64(a2, a3)), a4);

            // warp argmin: redux on hi word, then lo word among hi-winners
            unsigned hi   = (unsigned)(mloc >> 32);
            unsigned hmin = __reduce_min_sync(FULLMASK, hi);
            unsigned lo   = (hi == hmin) ? (unsigned)mloc : 0xFFFFFFFFu;
            unsigned lmin = __reduce_min_sync(FULLMASK, lo);

            int jst = (int)(lmin & 511u);
            unsigned long long mk = ((unsigned long long)hmin << 32) | (lmin & ~511u);
            minval = key2d(mk);

            // owner removes column jst (no sync needed: all lanes know jst)
            if ((jst & 31) == lane) {
                int slot = jst >> 5;
                rem      &= ~(1u << slot);
                remRound |=  (1u << slot);
                #pragma unroll
                for (int k = 0; k < NSLOT; k++) if (k == slot) skey[k] = ~0ULL;
            }

            int    rr = r4c[jst];
            double uu = urow[jst];
            if (rr < 0) { sink = jst; break; }
            i  = rr;
            ui = uu;
            SR |= 1ULL << i;
        }

        __syncwarp();   // spath/pb writes + r4c reads complete

        // dual updates: u for visited rows
        for (int m = lane; m < MM; m += 32) {
            if (m == cur) {
                su[m] += minval;
            } else if ((SR >> m) & 1) {
                int j2 = c4r[m];
                su[m] += minval - spath[j2];
            }
        }
        // dual updates: v for columns removed this round (own registers, own spath slots)
        #pragma unroll
        for (int k = 0; k < NSLOT; k++) {
            if (remRound & (1u << k)) {
                int j = k * 32 + lane;
                v[k] -= (minval - spath[j]);
            }
        }
        __syncwarp();

        // augment along pathback (lane 0)
        if (lane == 0) {
            int j = sink;
            while (true) {
                int ii = pb[j];
                r4c[j] = ii;
                int t = c4r[ii];
                c4r[ii] = j;
                j = t;
                if (ii == cur) break;
            }
        }
        __syncwarp();

        // refresh urow cache for matched columns (u changed for SR rows; cheap to do all)
        for (int m = lane; m < MM; m += 32) {
            int jm = c4r[m];
            if (jm >= 0) urow[jm] = su[m];
        }
        __syncwarp();
    }

    // ---- Per-image loss partials ----
    double pos = 0.0, obj = 0.0, noobj = 0.0;
    for (int m = lane; m < MM; m += 32) {
        int j = c4r[m];
        double dx = fabs((double)pc[2 * j]     - (double)gc[2 * m]);
        double dy = fabs((double)pc[2 * j + 1] - (double)gc[2 * m + 1]);
        pos += dx + dy;
        obj += softplus_d(-(double)cf[j]);
    }
    #pragma unroll
    for (int k = 0; k < NSLOT; k++) {
        int j = k * 32 + lane;
        if (j < NN && r4c[j] < 0)
            noobj += softplus_d((double)cf[j]);
    }
    #pragma unroll
    for (int off = 16; off; off >>= 1) {
        pos   += __shfl_xor_sync(FULLMASK, pos,   off);
        obj   += __shfl_xor_sync(FULLMASK, obj,   off);
        noobj += __shfl_xor_sync(FULLMASK, noobj, off);
    }
    int islast = 0;
    if (lane == 0) {
        g_part[b * 3 + 0] = pos   / (double)(MM * 2);
        g_part[b * 3 + 1] = obj   / (double)MM;
        g_part[b * 3 + 2] = noobj / (double)(NN - MM);
        __threadfence();
        int t = atomicAdd(&g_done, 1);
        islast = (t == BB - 1);
    }
    islast = __shfl_sync(FULLMASK, islast, 0);

    // last block finalizes (fused: saves a second kernel launch)
    if (islast) {
        __threadfence();
        double p = 0.0, o = 0.0, q = 0.0;
        if (lane < BB) {
            p = g_part[lane * 3 + 0];
            o = g_part[lane * 3 + 1];
            q = g_part[lane * 3 + 2];
        }
        #pragma unroll
        for (int off = 16; off; off >>= 1) {
            p += __shfl_xor_sync(FULLMASK, p, off);
            o += __shfl_xor_sync(FULLMASK, o, off);
            q += __shfl_xor_sync(FULLMASK, q, off);
        }
        if (lane == 0) {
            float lp = (float)(LAMBDA_POS   * p / (double)BB);
            float lo = (float)(LAMBDA_CONF  * o / (double)BB);
            float ln = (float)(LAMBDA_NOOBJ * q / (double)BB);
            out[0] = lp;
            out[1] = lo;
            out[2] = ln;
            out[3] = lp + lo + ln;
            out[4] = (float)MM;
            g_done = 0;   // self-reset for next (graph) replay
        }
    }
}

extern "C" void kernel_launch(void* const* d_in, const int* in_sizes, int n_in,
                              void* d_out, int out_size)
{
    // metadata order: pred_centroids, pred_logits, pred_conf, gt_centroids, gt_classes
    const float* pred_c = (const float*)d_in[0];
    const float* conf   = (const float*)d_in[2];
    const float* gt_c   = (const float*)d_in[3];
    float* out = (float*)d_out;

    cudaFuncSetAttribute(detloss_kernel,
                         cudaFuncAttributeMaxDynamicSharedMemorySize, SMEM_BYTES);
    detloss_kernel<<<BB, 32, SMEM_BYTES>>>(pred_c, conf, gt_c, out);
}

// round 5
// speedup vs baseline: 2.3352x; 1.3163x over previous
#include <cuda_runtime.h>
#include <cuda_bf16.h>
#include <math.h>
#include <float.h>

// Fixed problem shapes
#define BB 32
#define NN 300
#define MM 50
#define NSLOT 10          // columns per lane: lanes 0..11 own 10, lanes 12..31 own 9

#define LAMBDA_POS 5.0
#define LAMBDA_CONF 2.0
#define LAMBDA_NOOBJ 0.5

#define FULLMASK 0xffffffffu

// Cross-block scratch (no cudaMalloc allowed)
__device__ double g_part[BB * 3];
__device__ int    g_done = 0;

// ---- order-preserving double <-> u64 key transforms ----
__device__ __forceinline__ unsigned long long d2key(double d) {
    long long b = __double_as_longlong(d);
    unsigned long long ub = (unsigned long long)b;
    return (b >= 0) ? (ub ^ 0x8000000000000000ULL) : ~ub;
}
__device__ __forceinline__ double key2d(unsigned long long k) {
    unsigned long long b = (k & 0x8000000000000000ULL) ? (k ^ 0x8000000000000000ULL) : ~k;
    return __longlong_as_double((long long)b);
}
__device__ __forceinline__ unsigned long long umin64(unsigned long long a, unsigned long long b) {
    return a < b ? a : b;
}
// warp argmin over packed u64 keys (index in low 9 bits): two u32 redux
__device__ __forceinline__ unsigned long long warp_min_key(unsigned long long mloc) {
    unsigned hi   = (unsigned)(mloc >> 32);
    unsigned hmin = __reduce_min_sync(FULLMASK, hi);
    unsigned lo   = (hi == hmin) ? (unsigned)mloc : 0xFFFFFFFFu;
    unsigned lmin = __reduce_min_sync(FULLMASK, lo);
    return ((unsigned long long)hmin << 32) | lmin;
}
__device__ __forceinline__ double softplus_d(double x) {
    return fmax(x, 0.0) + log1p(exp(-fabs(x)));
}

// Dynamic smem layout (doubles first for alignment)
#define SMEM_DOUBLES (MM * NN + NN + NN + MM)
#define SMEM_INTS    (NN + NN + MM)
#define SMEM_BYTES   (SMEM_DOUBLES * 8 + SMEM_INTS * 4)

__global__ void __launch_bounds__(32, 1)
detloss_kernel(const float* __restrict__ pred_c,  // [B,N,2]
               const float* __restrict__ conf,    // [B,N]
               const float* __restrict__ gt_c,    // [B,M,2]
               float* __restrict__ out)           // [5]
{
    const int b    = blockIdx.x;
    const int lane = threadIdx.x;

    const float* pc = pred_c + b * NN * 2;
    const float* cf = conf   + b * NN;
    const float* gc = gt_c   + b * MM * 2;

    extern __shared__ double dyn[];
    double* sc     = dyn;                 // [MM][NN] cost
    double* spath  = sc + MM * NN;        // [NN] exact shortest values
    double* urow   = spath + NN;          // [NN] u[row4col[j]] cache
    double* su     = urow + NN;           // [MM] dual u
    int*    pb     = (int*)(su + MM);     // [NN] pathback
    int*    r4c    = pb + NN;             // [NN] row4col (-1 = free)
    int*    c4r    = r4c + NN;            // [MM] col4row (-1 = unassigned)

    // ---- Build cost matrix: cost[m][j] = 5*L1(pred_j, gt_m) - sigmoid(conf_j)
    // Column j is built AND consumed by lane (j % 32): no sync needed on sc.
    #pragma unroll
    for (int k = 0; k < NSLOT; k++) {
        int j = k * 32 + lane;
        if (j < NN) {
            double x   = (double)cf[j];
            double sig = 1.0 / (1.0 + exp(-x));
            double px  = (double)pc[2 * j];
            double py  = (double)pc[2 * j + 1];
            for (int m = 0; m < MM; m++) {
                double dx = fabs(px - (double)gc[2 * m]);
                double dy = fabs(py - (double)gc[2 * m + 1]);
                sc[m * NN + j] = 5.0 * (dx + dy) - sig;
            }
        }
    }
    for (int j = lane; j < NN; j += 32) { r4c[j] = -1; urow[j] = 0.0; }
    for (int m = lane; m < MM; m += 32) { su[m] = 0.0; c4r[m] = -1; }
    __syncwarp();

    // per-lane register duals for owned columns
    double v[NSLOT];
    #pragma unroll
    for (int k = 0; k < NSLOT; k++) v[k] = 0.0;
    const unsigned validMask = (lane < 12) ? 0x3FFu : 0x1FFu;

    // ==== Phase 1: LAPJV init — row reduction + greedy assignment ====
    // u[i] = min_j cost[i,j]; assign i -> argmin column if still free.
    // All-lanes-write trick: every lane writes the same value, so each lane's
    // own write is visible to itself next iteration without __syncwarp.
    for (int i = 0; i < MM; i++) {
        const double* crow = sc + i * NN;
        unsigned long long best = ~0ULL;
        #pragma unroll
        for (int k = 0; k < NSLOT; k++) {
            if (validMask & (1u << k)) {
                int j = k * 32 + lane;
                unsigned long long ck = (d2key(crow[j]) & ~511ULL) | (unsigned)j;
                best = umin64(best, ck);
            }
        }
        unsigned long long mk = warp_min_key(best);
        int    jmin   = (int)(mk & 511u);
        double rowmin = key2d(mk & ~511ULL);
        su[i] = rowmin;                      // same value from all lanes
        if (r4c[jmin] < 0) {                 // column free -> assign
            r4c[jmin] = i;
            c4r[i]    = jmin;
            urow[jmin] = rowmin;
        }
    }
    __syncwarp();

    // ==== Phase 2: shortest augmenting path for unassigned rows only ====
    for (int cur = 0; cur < MM; cur++) {
        if (c4r[cur] >= 0) continue;

        unsigned long long skey[NSLOT];
        #pragma unroll
        for (int k = 0; k < NSLOT; k++) skey[k] = ~0ULL;
        unsigned rem = validMask;
        unsigned remRound = 0;
        unsigned long long SR = 1ULL << cur;

        int    i      = cur;
        double ui     = su[cur];
        double minval = 0.0;
        int    sink;

        while (true) {
            double a = minval - ui;
            const double* crow = sc + i * NN;

            #pragma unroll
            for (int k = 0; k < NSLOT; k++) {
                if (rem & (1u << k)) {
                    int j = k * 32 + lane;
                    double nc = a + (crow[j] - v[k]);
                    unsigned long long ck = (d2key(nc) & ~511ULL) | (unsigned)j;
                    if (ck < skey[k]) {
                        skey[k] = ck;
                        spath[j] = nc;
                        pb[j]   = i;
                    }
                }
            }
            unsigned long long a0 = umin64(skey[0], skey[1]);
            unsigned long long a1 = umin64(skey[2], skey[3]);
            unsigned long long a2 = umin64(skey[4], skey[5]);
            unsigned long long a3 = umin64(skey[6], skey[7]);
            unsigned long long a4 = umin64(skey[8], skey[9]);
            unsigned long long mloc = umin64(umin64(umin64(a0, a1), umin64(a2, a3)), a4);

            unsigned long long mk = warp_min_key(mloc);
            int jst = (int)(mk & 511u);
            minval  = key2d(mk & ~511ULL);

            if ((jst & 31) == lane) {        // owner clears its column locally
                int slot = jst >> 5;
                rem      &= ~(1u << slot);
                remRound |=  (1u << slot);
                #pragma unroll
                for (int k = 0; k < NSLOT; k++) if (k == slot) skey[k] = ~0ULL;
            }

            int    rr = r4c[jst];
            double uu = urow[jst];
            if (rr < 0) { sink = jst; break; }
            i  = rr;
            ui = uu;
            SR |= 1ULL << i;
        }

        __syncwarp();

        // dual updates
        for (int m = lane; m < MM; m += 32) {
            if (m == cur) {
                su[m] += minval;
            } else if ((SR >> m) & 1) {
                su[m] += minval - spath[c4r[m]];
            }
        }
        #pragma unroll
        for (int k = 0; k < NSLOT; k++) {
            if (remRound & (1u << k)) {
                int j = k * 32 + lane;
                v[k] -= (minval - spath[j]);
            }
        }
        __syncwarp();

        // augment (lane 0)
        if (lane == 0) {
            int j = sink;
            while (true) {
                int ii = pb[j];
                r4c[j] = ii;
                int t = c4r[ii];
                c4r[ii] = j;
                j = t;
                if (ii == cur) break;
            }
        }
        __syncwarp();

        // refresh urow cache for matched columns
        for (int m = lane; m < MM; m += 32) {
            int jm = c4r[m];
            if (jm >= 0) urow[jm] = su[m];
        }
        __syncwarp();
    }

    // ==== Loss partials ====
    double pos = 0.0, obj = 0.0, noobj = 0.0;
    for (int m = lane; m < MM; m += 32) {
        int j = c4r[m];
        double dx = fabs((double)pc[2 * j]     - (double)gc[2 * m]);
        double dy = fabs((double)pc[2 * j + 1] - (double)gc[2 * m + 1]);
        pos += dx + dy;
        obj += softplus_d(-(double)cf[j]);
    }
    #pragma unroll
    for (int k = 0; k < NSLOT; k++) {
        int j = k * 32 + lane;
        if (j < NN && r4c[j] < 0)
            noobj += softplus_d((double)cf[j]);
    }
    #pragma unroll
    for (int off = 16; off; off >>= 1) {
        pos   += __shfl_xor_sync(FULLMASK, pos,   off);
        obj   += __shfl_xor_sync(FULLMASK, obj,   off);
        noobj += __shfl_xor_sync(FULLMASK, noobj, off);
    }
    int islast = 0;
    if (lane == 0) {
        g_part[b * 3 + 0] = pos   / (double)(MM * 2);
        g_part[b * 3 + 1] = obj   / (double)MM;
        g_part[b * 3 + 2] = noobj / (double)(NN - MM);
        __threadfence();
        int t = atomicAdd(&g_done, 1);
        islast = (t == BB - 1);
    }
    islast = __shfl_sync(FULLMASK, islast, 0);

    if (islast) {
        __threadfence();
        double p = 0.0, o = 0.0, q = 0.0;
        if (lane < BB) {
            p = g_part[lane * 3 + 0];
            o = g_part[lane * 3 + 1];
            q = g_part[lane * 3 + 2];
        }
        #pragma unroll
        for (int off = 16; off; off >>= 1) {
            p += __shfl_xor_sync(FULLMASK, p, off);
            o += __shfl_xor_sync(FULLMASK, o, off);
            q += __shfl_xor_sync(FULLMASK, q, off);
        }
        if (lane == 0) {
            float lp = (float)(LAMBDA_POS   * p / (double)BB);
            float lo = (float)(LAMBDA_CONF  * o / (double)BB);
            float ln = (float)(LAMBDA_NOOBJ * q / (double)BB);
            out[0] = lp;
            out[1] = lo;
            out[2] = ln;
            out[3] = lp + lo + ln;
            out[4] = (float)MM;
            g_done = 0;   // self-reset for next graph replay
        }
    }
}

extern "C" void kernel_launch(void* const* d_in, const int* in_sizes, int n_in,
                              void* d_out, int out_size)
{
    const float* pred_c = (const float*)d_in[0];
    const float* conf   = (const float*)d_in[2];
    const float* gt_c   = (const float*)d_in[3];
    float* out = (float*)d_out;

    cudaFuncSetAttribute(detloss_kernel,
                         cudaFuncAttributeMaxDynamicSharedMemorySize, SMEM_BYTES);
    detloss_kernel<<<BB, 32, SMEM_BYTES>>>(pred_c, conf, gt_c, out);
}